// round 6
// baseline (speedup 1.0000x reference)
#include <cuda_runtime.h>
#include <cuda_bf16.h>
#include <cstdint>

#define T_SEQ   2048
#define BATCH   2
#define DM      512
#define NROWS   (BATCH * T_SEQ)   // 4096
#define QKV_N   (3 * DM)          // 1536
#define WIN     32
#define WW      (2 * WIN - 1)     // 63

// ---------------- scratch (__device__ globals: allocation-free rule) -------
__device__ float g_qkv[NROWS * QKV_N];           // fp32 q|k|v for attention
__device__ __nv_bfloat16 g_xh[NROWS * DM],  g_xl[NROWS * DM];
__device__ __nv_bfloat16 g_wqh[QKV_N * DM], g_wql[QKV_N * DM];
__device__ __nv_bfloat16 g_wph[DM * DM],    g_wpl[DM * DM];
__device__ __nv_bfloat16 g_ah[NROWS * DM],  g_al[NROWS * DM];

// ---------------- helpers ---------------------------------------------------
__device__ __forceinline__ uint32_t smem_u32(const void* p) {
    uint32_t a;
    asm("{ .reg .u64 t; cvta.to.shared.u64 t, %1; cvt.u32.u64 %0, t; }"
        : "=r"(a) : "l"(p));
    return a;
}

__device__ __forceinline__ void mma_bf16(float* c, const uint32_t* a, const uint32_t* b) {
    asm volatile(
        "mma.sync.aligned.m16n8k16.row.col.f32.bf16.bf16.f32 "
        "{%0,%1,%2,%3}, {%4,%5,%6,%7}, {%8,%9}, {%0,%1,%2,%3};"
        : "+f"(c[0]), "+f"(c[1]), "+f"(c[2]), "+f"(c[3])
        : "r"(a[0]), "r"(a[1]), "r"(a[2]), "r"(a[3]), "r"(b[0]), "r"(b[1]));
}

__device__ __forceinline__ void ldm_x4(uint32_t* d, uint32_t addr) {
    asm volatile("ldmatrix.sync.aligned.m8n8.x4.shared.b16 {%0,%1,%2,%3}, [%4];"
                 : "=r"(d[0]), "=r"(d[1]), "=r"(d[2]), "=r"(d[3]) : "r"(addr));
}
__device__ __forceinline__ void ldm_x2(uint32_t* d, uint32_t addr) {
    asm volatile("ldmatrix.sync.aligned.m8n8.x2.shared.b16 {%0,%1}, [%2];"
                 : "=r"(d[0]), "=r"(d[1]) : "r"(addr));
}

// smem geometry: K-chunk 32 bf16 (64B) + 16B pad -> 80B row stride.
#define ROWB   80
#define TILEB  (128 * ROWB)        // 10240 B per [128 x 32bf16] tile
#define STAGEB (4 * TILEB)         // Ah | Al | Bh | Bl = 40960 B
#define GEMM_SMEM (2 * STAGEB)     // 81920 B double buffered -> 2 CTAs/SM

// ---------------------------------------------------------------------------
// fp32 -> (hi, lo) bf16 split
// ---------------------------------------------------------------------------
__global__ __launch_bounds__(256) void split_bf16(
    const float4* __restrict__ src,
    __nv_bfloat16* __restrict__ hi, __nv_bfloat16* __restrict__ lo, int n4)
{
    int i = blockIdx.x * blockDim.x + threadIdx.x;
    if (i >= n4) return;
    float4 v = src[i];
    float xs[4] = {v.x, v.y, v.z, v.w};
    unsigned short h[4], l[4];
#pragma unroll
    for (int j = 0; j < 4; j++) {
        __nv_bfloat16 hb = __float2bfloat16(xs[j]);
        __nv_bfloat16 lb = __float2bfloat16(xs[j] - __bfloat162float(hb));
        h[j] = __bfloat16_as_ushort(hb);
        l[j] = __bfloat16_as_ushort(lb);
    }
    uint2 hv, lv;
    hv.x = h[0] | ((uint32_t)h[1] << 16);
    hv.y = h[2] | ((uint32_t)h[3] << 16);
    lv.x = l[0] | ((uint32_t)l[1] << 16);
    lv.y = l[2] | ((uint32_t)l[3] << 16);
    reinterpret_cast<uint2*>(hi)[i] = hv;
    reinterpret_cast<uint2*>(lo)[i] = lv;
}

// ---------------------------------------------------------------------------
// Split-bf16 HMMA GEMM: C[M,Ntot] = A[M,K] @ B[Ntot,K]^T + bias
// D = Ah*Bh + Al*Bh + Ah*Bl (fp32 accum). CTA 128x128, 8 warps x (64x32).
// Term-grouped inner loop: same-accumulator reuse distance 4 (was 1).
// ---------------------------------------------------------------------------
__global__ __launch_bounds__(256, 2) void gemm_split_mma(
    int Ntot, int kchunks,
    const __nv_bfloat16* __restrict__ Ah, const __nv_bfloat16* __restrict__ Al,
    const __nv_bfloat16* __restrict__ Bh, const __nv_bfloat16* __restrict__ Bl,
    const float* __restrict__ bias, float* __restrict__ C)
{
    extern __shared__ __align__(16) char smem[];
    const uint32_t sbase = smem_u32(smem);

    const int tid    = threadIdx.x;
    const int wid    = tid >> 5;
    const int lane   = tid & 31;
    const int l4     = lane >> 2;
    const int lq     = lane & 3;
    const int warp_m = (wid & 1) * 64;
    const int warp_n = (wid >> 1) * 32;
    const int m0     = blockIdx.y * 128;
    const int n0     = blockIdx.x * 128;
    const int K      = kchunks * 32;

    const __nv_bfloat16* srcs[4] = {Ah, Al, Bh, Bl};

    const int g8 = lane >> 3;
    const int r8 = lane & 7;
    const uint32_t a_off = (uint32_t)((warp_m + (g8 & 1) * 8 + r8) * ROWB + (g8 >> 1) * 16);
    const uint32_t b_off = (uint32_t)((warp_n + r8) * ROWB + ((lane >> 3) & 1) * 16);

    const int ld_row  = tid >> 1;
    const int ld_half = tid & 1;
    auto issue_stage = [&](int c, int buf) {
#pragma unroll
        for (int t = 0; t < 4; t++) {
            const int rbase = (t < 2) ? m0 : n0;
            const __nv_bfloat16* gp =
                srcs[t] + (size_t)(rbase + ld_row) * K + c * 32 + ld_half * 16;
            const uint32_t sa = sbase + buf * STAGEB + t * TILEB
                              + ld_row * ROWB + ld_half * 32;
#pragma unroll
            for (int j = 0; j < 2; j++)
                asm volatile("cp.async.cg.shared.global [%0], [%1], 16;"
                             :: "r"(sa + j * 16), "l"(gp + j * 8) : "memory");
        }
        asm volatile("cp.async.commit_group;" ::: "memory");
    };

    float acc[4][4][4];
#pragma unroll
    for (int i = 0; i < 4; i++)
#pragma unroll
        for (int j = 0; j < 4; j++)
#pragma unroll
            for (int r = 0; r < 4; r++) acc[i][j][r] = 0.0f;

    issue_stage(0, 0);
    if (kchunks > 1) issue_stage(1, 1);

    for (int c = 0; c < kchunks; c++) {
        const int buf = c & 1;
        if (c + 1 < kchunks) asm volatile("cp.async.wait_group 1;" ::: "memory");
        else                 asm volatile("cp.async.wait_group 0;" ::: "memory");
        __syncthreads();

        const uint32_t stage = sbase + buf * STAGEB;
        const uint32_t Abh = stage;
        const uint32_t Abl = stage + TILEB;
        const uint32_t Bbh = stage + 2 * TILEB;
        const uint32_t Bbl = stage + 3 * TILEB;

#pragma unroll
        for (int kk = 0; kk < 2; kk++) {
            uint32_t ah[4][4], al[4][4];
#pragma unroll
            for (int mt = 0; mt < 4; mt++) {
                const uint32_t o = a_off + mt * 16 * ROWB + kk * 32;
                ldm_x4(ah[mt], Abh + o);
                ldm_x4(al[mt], Abl + o);
            }
#pragma unroll
            for (int nt = 0; nt < 4; nt++) {
                const uint32_t o = b_off + nt * 8 * ROWB + kk * 32;
                uint32_t bh[2], bl[2];
                ldm_x2(bh, Bbh + o);
                ldm_x2(bl, Bbl + o);
                // term-grouped: acc reuse distance = 4 MMAs
#pragma unroll
                for (int mt = 0; mt < 4; mt++) mma_bf16(acc[mt][nt], ah[mt], bh);
#pragma unroll
                for (int mt = 0; mt < 4; mt++) mma_bf16(acc[mt][nt], al[mt], bh);
#pragma unroll
                for (int mt = 0; mt < 4; mt++) mma_bf16(acc[mt][nt], ah[mt], bl);
            }
        }

        __syncthreads();
        if (c + 2 < kchunks) issue_stage(c + 2, buf);
    }

    // ---- epilogue: fp32 + bias ----
#pragma unroll
    for (int nt = 0; nt < 4; nt++) {
        const int col = n0 + warp_n + nt * 8 + 2 * lq;
        const float2 bv = *reinterpret_cast<const float2*>(bias + col);
#pragma unroll
        for (int mt = 0; mt < 4; mt++) {
            const int row = m0 + warp_m + mt * 16 + l4;
            float2 r0, r1;
            r0.x = acc[mt][nt][0] + bv.x;
            r0.y = acc[mt][nt][1] + bv.y;
            r1.x = acc[mt][nt][2] + bv.x;
            r1.y = acc[mt][nt][3] + bv.y;
            *reinterpret_cast<float2*>(C + (size_t)row * Ntot + col) = r0;
            *reinterpret_cast<float2*>(C + (size_t)(row + 8) * Ntot + col) = r1;
        }
    }
}

// ---------------------------------------------------------------------------
// Local windowed attention: 1 warp = 4 rows (halves k/v L2 traffic vs 2 rows).
// Emits hi/lo bf16 split directly.
// ---------------------------------------------------------------------------
__global__ __launch_bounds__(256) void local_attn(
    const float* __restrict__ qkv,
    __nv_bfloat16* __restrict__ oh, __nv_bfloat16* __restrict__ ol)
{
    const int lane = threadIdx.x & 31;
    const int wg   = (blockIdx.x * blockDim.x + threadIdx.x) >> 5;
    const int m0   = wg * 4;
    const int t0   = m0 & (T_SEQ - 1);

    const float NEG = -1e30f;
    const float inv_scale = 1.0f / 22.62741699796952f;  // 1/sqrt(512)

    float4 q[4][4];
#pragma unroll
    for (int dt = 0; dt < 4; dt++) {
        const float* qp = qkv + (size_t)(m0 + dt) * QKV_N + lane * 4;
#pragma unroll
        for (int g = 0; g < 4; g++)
            q[dt][g] = *reinterpret_cast<const float4*>(qp + 128 * g);
    }

    float s[4][2];
#pragma unroll
    for (int dt = 0; dt < 4; dt++) { s[dt][0] = NEG; s[dt][1] = NEG; }

    // union window for rows t0..t0+3: d in [-(WIN-1), WIN+3-1+1] -> [-31, 34]
    for (int d = -(WIN - 1); d <= WIN + 3; d++) {
        const int rt = t0 + d;
        if (rt < 0 || rt >= T_SEQ) continue;
        const float* kp = qkv + (size_t)(m0 + d) * QKV_N + DM + lane * 4;
        float4 kr[4];
#pragma unroll
        for (int g = 0; g < 4; g++)
            kr[g] = *reinterpret_cast<const float4*>(kp + 128 * g);

#pragma unroll
        for (int dt = 0; dt < 4; dt++) {
            const int w = d - dt + (WIN - 1);
            if (w < 0 || w >= WW) continue;
            float dot = 0.0f;
#pragma unroll
            for (int g = 0; g < 4; g++) {
                dot = fmaf(q[dt][g].x, kr[g].x, dot);
                dot = fmaf(q[dt][g].y, kr[g].y, dot);
                dot = fmaf(q[dt][g].z, kr[g].z, dot);
                dot = fmaf(q[dt][g].w, kr[g].w, dot);
            }
#pragma unroll
            for (int o = 16; o > 0; o >>= 1)
                dot += __shfl_xor_sync(0xffffffffu, dot, o);
            if (lane == (w & 31)) s[dt][w >> 5] = dot;
        }
    }

#pragma unroll
    for (int dt = 0; dt < 4; dt++) {
        float s0 = s[dt][0] * inv_scale;
        float s1 = s[dt][1] * inv_scale;
        float mx = fmaxf(s0, s1);
#pragma unroll
        for (int o = 16; o > 0; o >>= 1)
            mx = fmaxf(mx, __shfl_xor_sync(0xffffffffu, mx, o));
        float e0 = __expf(s0 - mx);
        float e1 = __expf(s1 - mx);
        float sum = e0 + e1;
#pragma unroll
        for (int o = 16; o > 0; o >>= 1)
            sum += __shfl_xor_sync(0xffffffffu, sum, o);
        float inv = 1.0f / sum;
        s[dt][0] = e0 * inv;
        s[dt][1] = e1 * inv;
    }

    float4 o[4][4];
#pragma unroll
    for (int dt = 0; dt < 4; dt++)
#pragma unroll
        for (int g = 0; g < 4; g++)
            o[dt][g] = make_float4(0.f, 0.f, 0.f, 0.f);

    for (int d = -(WIN - 1); d <= WIN + 3; d++) {
        const int rt = t0 + d;
        if (rt < 0 || rt >= T_SEQ) continue;
        const float* vp = qkv + (size_t)(m0 + d) * QKV_N + 2 * DM + lane * 4;
        float4 vr[4];
#pragma unroll
        for (int g = 0; g < 4; g++)
            vr[g] = *reinterpret_cast<const float4*>(vp + 128 * g);

#pragma unroll
        for (int dt = 0; dt < 4; dt++) {
            const int w = d - dt + (WIN - 1);
            if (w < 0 || w >= WW) continue;
            const float p = __shfl_sync(0xffffffffu, s[dt][w >> 5], w & 31);
#pragma unroll
            for (int g = 0; g < 4; g++) {
                o[dt][g].x = fmaf(p, vr[g].x, o[dt][g].x);
                o[dt][g].y = fmaf(p, vr[g].y, o[dt][g].y);
                o[dt][g].z = fmaf(p, vr[g].z, o[dt][g].z);
                o[dt][g].w = fmaf(p, vr[g].w, o[dt][g].w);
            }
        }
    }

    // write hi/lo bf16 split directly
#pragma unroll
    for (int dt = 0; dt < 4; dt++) {
        const size_t base = (size_t)(m0 + dt) * DM + lane * 4;
#pragma unroll
        for (int g = 0; g < 4; g++) {
            float vals[4] = {o[dt][g].x, o[dt][g].y, o[dt][g].z, o[dt][g].w};
            unsigned short h[4], l[4];
#pragma unroll
            for (int j = 0; j < 4; j++) {
                __nv_bfloat16 hb = __float2bfloat16(vals[j]);
                __nv_bfloat16 lb = __float2bfloat16(vals[j] - __bfloat162float(hb));
                h[j] = __bfloat16_as_ushort(hb);
                l[j] = __bfloat16_as_ushort(lb);
            }
            uint2 hv, lv;
            hv.x = h[0] | ((uint32_t)h[1] << 16);
            hv.y = h[2] | ((uint32_t)h[3] << 16);
            lv.x = l[0] | ((uint32_t)l[1] << 16);
            lv.y = l[2] | ((uint32_t)l[3] << 16);
            *reinterpret_cast<uint2*>(oh + base + 128 * g) = hv;
            *reinterpret_cast<uint2*>(ol + base + 128 * g) = lv;
        }
    }
}

// ---------------------------------------------------------------------------
extern "C" void kernel_launch(void* const* d_in, const int* in_sizes, int n_in,
                              void* d_out, int out_size)
{
    const float* x      = (const float*)d_in[0];
    const float* w_qkv  = (const float*)d_in[1];
    const float* b_qkv  = (const float*)d_in[2];
    const float* w_proj = (const float*)d_in[3];
    const float* b_proj = (const float*)d_in[4];
    float* out = (float*)d_out;

    float* qkv;
    __nv_bfloat16 *xh, *xl, *wqh, *wql, *wph, *wpl, *ah, *al;
    cudaGetSymbolAddress((void**)&qkv, g_qkv);
    cudaGetSymbolAddress((void**)&xh,  g_xh);
    cudaGetSymbolAddress((void**)&xl,  g_xl);
    cudaGetSymbolAddress((void**)&wqh, g_wqh);
    cudaGetSymbolAddress((void**)&wql, g_wql);
    cudaGetSymbolAddress((void**)&wph, g_wph);
    cudaGetSymbolAddress((void**)&wpl, g_wpl);
    cudaGetSymbolAddress((void**)&ah,  g_ah);
    cudaGetSymbolAddress((void**)&al,  g_al);

    static bool attr_set = false;
    if (!attr_set) {
        cudaFuncSetAttribute(gemm_split_mma,
                             cudaFuncAttributeMaxDynamicSharedMemorySize, GEMM_SMEM);
        attr_set = true;
    }

    // 0) precision splits
    split_bf16<<<(NROWS * DM / 4 + 255) / 256, 256>>>((const float4*)x, xh, xl, NROWS * DM / 4);
    split_bf16<<<(QKV_N * DM / 4 + 255) / 256, 256>>>((const float4*)w_qkv, wqh, wql, QKV_N * DM / 4);
    split_bf16<<<(DM * DM / 4 + 255) / 256, 256>>>((const float4*)w_proj, wph, wpl, DM * DM / 4);

    // 1) qkv = x @ w_qkv^T + b_qkv   [4096,1536]  (HMMA split-bf16)
    gemm_split_mma<<<dim3(QKV_N / 128, NROWS / 128), 256, GEMM_SMEM>>>(
        QKV_N, DM / 32, xh, xl, wqh, wql, b_qkv, qkv);

    // 2) local windowed attention -> hi/lo bf16 [4096,512]  (4 rows/warp)
    local_attn<<<NROWS / 4 / 8, 256>>>(qkv, ah, al);

    // 3) out = att @ w_proj^T + b_proj
    gemm_split_mma<<<dim3(DM / 128, NROWS / 128), 256, GEMM_SMEM>>>(
        DM, DM / 32, ah, al, wph, wpl, b_proj, out);
}

// round 7
// speedup vs baseline: 1.1146x; 1.1146x over previous
#include <cuda_runtime.h>
#include <cuda_bf16.h>
#include <cstdint>

#define T_SEQ   2048
#define BATCH   2
#define DM      512
#define NROWS   (BATCH * T_SEQ)   // 4096
#define QKV_N   (3 * DM)          // 1536
#define WIN     32
#define WW      (2 * WIN - 1)     // 63

// ---------------- scratch (__device__ globals: allocation-free rule) -------
__device__ float g_qkv[NROWS * QKV_N];           // fp32 q|k|v for attention
__device__ __nv_bfloat16 g_xh[NROWS * DM],  g_xl[NROWS * DM];
__device__ __nv_bfloat16 g_wqh[QKV_N * DM], g_wql[QKV_N * DM];
__device__ __nv_bfloat16 g_wph[DM * DM],    g_wpl[DM * DM];
__device__ __nv_bfloat16 g_ah[NROWS * DM],  g_al[NROWS * DM];

// ---------------- helpers ---------------------------------------------------
__device__ __forceinline__ uint32_t smem_u32(const void* p) {
    uint32_t a;
    asm("{ .reg .u64 t; cvta.to.shared.u64 t, %1; cvt.u32.u64 %0, t; }"
        : "=r"(a) : "l"(p));
    return a;
}

__device__ __forceinline__ void mma_bf16(float* c, const uint32_t* a, const uint32_t* b) {
    asm volatile(
        "mma.sync.aligned.m16n8k16.row.col.f32.bf16.bf16.f32 "
        "{%0,%1,%2,%3}, {%4,%5,%6,%7}, {%8,%9}, {%0,%1,%2,%3};"
        : "+f"(c[0]), "+f"(c[1]), "+f"(c[2]), "+f"(c[3])
        : "r"(a[0]), "r"(a[1]), "r"(a[2]), "r"(a[3]), "r"(b[0]), "r"(b[1]));
}

__device__ __forceinline__ void ldm_x4(uint32_t* d, uint32_t addr) {
    asm volatile("ldmatrix.sync.aligned.m8n8.x4.shared.b16 {%0,%1,%2,%3}, [%4];"
                 : "=r"(d[0]), "=r"(d[1]), "=r"(d[2]), "=r"(d[3]) : "r"(addr));
}
__device__ __forceinline__ void ldm_x2(uint32_t* d, uint32_t addr) {
    asm volatile("ldmatrix.sync.aligned.m8n8.x2.shared.b16 {%0,%1}, [%2];"
                 : "=r"(d[0]), "=r"(d[1]) : "r"(addr));
}

// smem geometry: K-chunk 32 bf16 (64B) + 16B pad -> 80B row stride.
#define ROWB    80
#define TILEB_A (128 * ROWB)       // 10240 B : [128 x 32bf16]
#define TILEB_B (64  * ROWB)       // 5120  B : [64  x 32bf16]
#define STAGEB  (2 * TILEB_A + 2 * TILEB_B)   // Ah|Al|Bh|Bl = 30720 B
#define GEMM_SMEM (2 * STAGEB)                // 61440 B double buffered

// ---------------------------------------------------------------------------
// fp32 -> (hi, lo) bf16 split
// ---------------------------------------------------------------------------
__global__ __launch_bounds__(256) void split_bf16(
    const float4* __restrict__ src,
    __nv_bfloat16* __restrict__ hi, __nv_bfloat16* __restrict__ lo, int n4)
{
    int i = blockIdx.x * blockDim.x + threadIdx.x;
    if (i >= n4) return;
    float4 v = src[i];
    float xs[4] = {v.x, v.y, v.z, v.w};
    unsigned short h[4], l[4];
#pragma unroll
    for (int j = 0; j < 4; j++) {
        __nv_bfloat16 hb = __float2bfloat16(xs[j]);
        __nv_bfloat16 lb = __float2bfloat16(xs[j] - __bfloat162float(hb));
        h[j] = __bfloat16_as_ushort(hb);
        l[j] = __bfloat16_as_ushort(lb);
    }
    uint2 hv, lv;
    hv.x = h[0] | ((uint32_t)h[1] << 16);
    hv.y = h[2] | ((uint32_t)h[3] << 16);
    lv.x = l[0] | ((uint32_t)l[1] << 16);
    lv.y = l[2] | ((uint32_t)l[3] << 16);
    reinterpret_cast<uint2*>(hi)[i] = hv;
    reinterpret_cast<uint2*>(lo)[i] = lv;
}

// ---------------------------------------------------------------------------
// Split-bf16 HMMA GEMM: C[M,Ntot] = A[M,K] @ B[Ntot,K]^T + bias
// D = Ah*Bh + Al*Bh + Ah*Bl (fp32 accum).
// CTA tile 128x64 (anti wave-quantization), 8 warps x (32x32).
// ---------------------------------------------------------------------------
__global__ __launch_bounds__(256, 2) void gemm_split_mma(
    int Ntot, int kchunks,
    const __nv_bfloat16* __restrict__ Ah, const __nv_bfloat16* __restrict__ Al,
    const __nv_bfloat16* __restrict__ Bh, const __nv_bfloat16* __restrict__ Bl,
    const float* __restrict__ bias, float* __restrict__ C)
{
    extern __shared__ __align__(16) char smem[];
    const uint32_t sbase = smem_u32(smem);

    const int tid    = threadIdx.x;
    const int wid    = tid >> 5;
    const int lane   = tid & 31;
    const int l4     = lane >> 2;
    const int lq     = lane & 3;
    const int warp_m = (wid & 3) * 32;      // 4 groups of 32 rows
    const int warp_n = (wid >> 2) * 32;     // 2 groups of 32 cols
    const int m0     = blockIdx.y * 128;
    const int n0     = blockIdx.x * 64;
    const int K      = kchunks * 32;

    const __nv_bfloat16* srcs[4] = {Ah, Al, Bh, Bl};
    const uint32_t toff[4] = {0u, TILEB_A, 2u * TILEB_A, 2u * TILEB_A + TILEB_B};

    const int g8 = lane >> 3;
    const int r8 = lane & 7;
    const uint32_t a_off = (uint32_t)((warp_m + (g8 & 1) * 8 + r8) * ROWB + (g8 >> 1) * 16);
    const uint32_t b_off = (uint32_t)((warp_n + r8) * ROWB + ((lane >> 3) & 1) * 16);

    // stage loader: 6 granule batches (Ah x2, Al x2, Bh, Bl), 16B each
    auto issue_stage = [&](int c, int buf) {
        const int rt[6]   = {0, 0, 1, 1, 2, 3};
        const int gofs[6] = {0, 256, 0, 256, 0, 0};
#pragma unroll
        for (int j = 0; j < 6; j++) {
            const int t   = rt[j];
            const int g   = tid + gofs[j];
            const int row = g >> 2;
            const int c16 = g & 3;
            const int rbase = (t < 2) ? m0 : n0;
            const __nv_bfloat16* gp =
                srcs[t] + (size_t)(rbase + row) * K + c * 32 + c16 * 8;
            const uint32_t sa = sbase + buf * STAGEB + toff[t]
                              + row * ROWB + c16 * 16;
            asm volatile("cp.async.cg.shared.global [%0], [%1], 16;"
                         :: "r"(sa), "l"(gp) : "memory");
        }
        asm volatile("cp.async.commit_group;" ::: "memory");
    };

    float acc[2][4][4];
#pragma unroll
    for (int i = 0; i < 2; i++)
#pragma unroll
        for (int j = 0; j < 4; j++)
#pragma unroll
            for (int r = 0; r < 4; r++) acc[i][j][r] = 0.0f;

    issue_stage(0, 0);
    if (kchunks > 1) issue_stage(1, 1);

    for (int c = 0; c < kchunks; c++) {
        const int buf = c & 1;
        if (c + 1 < kchunks) asm volatile("cp.async.wait_group 1;" ::: "memory");
        else                 asm volatile("cp.async.wait_group 0;" ::: "memory");
        __syncthreads();

        const uint32_t stage = sbase + buf * STAGEB;
        const uint32_t Abh = stage;
        const uint32_t Abl = stage + TILEB_A;
        const uint32_t Bbh = stage + 2 * TILEB_A;
        const uint32_t Bbl = stage + 2 * TILEB_A + TILEB_B;

#pragma unroll
        for (int kk = 0; kk < 2; kk++) {
            uint32_t ah[2][4], al[2][4];
#pragma unroll
            for (int mt = 0; mt < 2; mt++) {
                const uint32_t o = a_off + mt * 16 * ROWB + kk * 32;
                ldm_x4(ah[mt], Abh + o);
                ldm_x4(al[mt], Abl + o);
            }
#pragma unroll
            for (int nt = 0; nt < 4; nt++) {
                const uint32_t o = b_off + nt * 8 * ROWB + kk * 32;
                uint32_t bh[2], bl[2];
                ldm_x2(bh, Bbh + o);
                ldm_x2(bl, Bbl + o);
#pragma unroll
                for (int mt = 0; mt < 2; mt++) mma_bf16(acc[mt][nt], ah[mt], bh);
#pragma unroll
                for (int mt = 0; mt < 2; mt++) mma_bf16(acc[mt][nt], al[mt], bh);
#pragma unroll
                for (int mt = 0; mt < 2; mt++) mma_bf16(acc[mt][nt], ah[mt], bl);
            }
        }

        __syncthreads();
        if (c + 2 < kchunks) issue_stage(c + 2, buf);
    }

    // ---- epilogue: fp32 + bias ----
#pragma unroll
    for (int nt = 0; nt < 4; nt++) {
        const int col = n0 + warp_n + nt * 8 + 2 * lq;
        const float2 bv = *reinterpret_cast<const float2*>(bias + col);
#pragma unroll
        for (int mt = 0; mt < 2; mt++) {
            const int row = m0 + warp_m + mt * 16 + l4;
            float2 r0, r1;
            r0.x = acc[mt][nt][0] + bv.x;
            r0.y = acc[mt][nt][1] + bv.y;
            r1.x = acc[mt][nt][2] + bv.x;
            r1.y = acc[mt][nt][3] + bv.y;
            *reinterpret_cast<float2*>(C + (size_t)row * Ntot + col) = r0;
            *reinterpret_cast<float2*>(C + (size_t)(row + 8) * Ntot + col) = r1;
        }
    }
}

// ---------------------------------------------------------------------------
// Local windowed attention (R5 version): 1 warp = 2 rows, float4 loads,
// emits hi/lo bf16 split directly.
// ---------------------------------------------------------------------------
__global__ __launch_bounds__(256) void local_attn(
    const float* __restrict__ qkv,
    __nv_bfloat16* __restrict__ oh, __nv_bfloat16* __restrict__ ol)
{
    const int lane = threadIdx.x & 31;
    const int wg   = (blockIdx.x * blockDim.x + threadIdx.x) >> 5;
    const int m0   = wg * 2;
    const int t0   = m0 & (T_SEQ - 1);

    const float NEG = -1e30f;
    const float inv_scale = 1.0f / 22.62741699796952f;  // 1/sqrt(512)

    float4 q[2][4];
#pragma unroll
    for (int dt = 0; dt < 2; dt++) {
        const float* qp = qkv + (size_t)(m0 + dt) * QKV_N + lane * 4;
#pragma unroll
        for (int g = 0; g < 4; g++)
            q[dt][g] = *reinterpret_cast<const float4*>(qp + 128 * g);
    }

    float s[2][2] = {{NEG, NEG}, {NEG, NEG}};

    for (int d = -(WIN - 1); d <= WIN; d++) {
        const int rt = t0 + d;
        if (rt < 0 || rt >= T_SEQ) continue;
        const float* kp = qkv + (size_t)(m0 + d) * QKV_N + DM + lane * 4;
        float4 kr[4];
#pragma unroll
        for (int g = 0; g < 4; g++)
            kr[g] = *reinterpret_cast<const float4*>(kp + 128 * g);

#pragma unroll
        for (int dt = 0; dt < 2; dt++) {
            const int w = d - dt + (WIN - 1);
            if (w < 0 || w >= WW) continue;
            float dot = 0.0f;
#pragma unroll
            for (int g = 0; g < 4; g++) {
                dot = fmaf(q[dt][g].x, kr[g].x, dot);
                dot = fmaf(q[dt][g].y, kr[g].y, dot);
                dot = fmaf(q[dt][g].z, kr[g].z, dot);
                dot = fmaf(q[dt][g].w, kr[g].w, dot);
            }
#pragma unroll
            for (int o = 16; o > 0; o >>= 1)
                dot += __shfl_xor_sync(0xffffffffu, dot, o);
            if (lane == (w & 31)) s[dt][w >> 5] = dot;
        }
    }

#pragma unroll
    for (int dt = 0; dt < 2; dt++) {
        float s0 = s[dt][0] * inv_scale;
        float s1 = s[dt][1] * inv_scale;
        float mx = fmaxf(s0, s1);
#pragma unroll
        for (int o = 16; o > 0; o >>= 1)
            mx = fmaxf(mx, __shfl_xor_sync(0xffffffffu, mx, o));
        float e0 = __expf(s0 - mx);
        float e1 = __expf(s1 - mx);
        float sum = e0 + e1;
#pragma unroll
        for (int o = 16; o > 0; o >>= 1)
            sum += __shfl_xor_sync(0xffffffffu, sum, o);
        float inv = 1.0f / sum;
        s[dt][0] = e0 * inv;
        s[dt][1] = e1 * inv;
    }

    float4 o[2][4];
#pragma unroll
    for (int dt = 0; dt < 2; dt++)
#pragma unroll
        for (int g = 0; g < 4; g++)
            o[dt][g] = make_float4(0.f, 0.f, 0.f, 0.f);

    for (int d = -(WIN - 1); d <= WIN; d++) {
        const int rt = t0 + d;
        if (rt < 0 || rt >= T_SEQ) continue;
        const float* vp = qkv + (size_t)(m0 + d) * QKV_N + 2 * DM + lane * 4;
        float4 vr[4];
#pragma unroll
        for (int g = 0; g < 4; g++)
            vr[g] = *reinterpret_cast<const float4*>(vp + 128 * g);

#pragma unroll
        for (int dt = 0; dt < 2; dt++) {
            const int w = d - dt + (WIN - 1);
            if (w < 0 || w >= WW) continue;
            const float p = __shfl_sync(0xffffffffu, s[dt][w >> 5], w & 31);
#pragma unroll
            for (int g = 0; g < 4; g++) {
                o[dt][g].x = fmaf(p, vr[g].x, o[dt][g].x);
                o[dt][g].y = fmaf(p, vr[g].y, o[dt][g].y);
                o[dt][g].z = fmaf(p, vr[g].z, o[dt][g].z);
                o[dt][g].w = fmaf(p, vr[g].w, o[dt][g].w);
            }
        }
    }

    // write hi/lo bf16 split directly
#pragma unroll
    for (int dt = 0; dt < 2; dt++) {
        const size_t base = (size_t)(m0 + dt) * DM + lane * 4;
#pragma unroll
        for (int g = 0; g < 4; g++) {
            float vals[4] = {o[dt][g].x, o[dt][g].y, o[dt][g].z, o[dt][g].w};
            unsigned short h[4], l[4];
#pragma unroll
            for (int j = 0; j < 4; j++) {
                __nv_bfloat16 hb = __float2bfloat16(vals[j]);
                __nv_bfloat16 lb = __float2bfloat16(vals[j] - __bfloat162float(hb));
                h[j] = __bfloat16_as_ushort(hb);
                l[j] = __bfloat16_as_ushort(lb);
            }
            uint2 hv, lv;
            hv.x = h[0] | ((uint32_t)h[1] << 16);
            hv.y = h[2] | ((uint32_t)h[3] << 16);
            lv.x = l[0] | ((uint32_t)l[1] << 16);
            lv.y = l[2] | ((uint32_t)l[3] << 16);
            *reinterpret_cast<uint2*>(oh + base + 128 * g) = hv;
            *reinterpret_cast<uint2*>(ol + base + 128 * g) = lv;
        }
    }
}

// ---------------------------------------------------------------------------
extern "C" void kernel_launch(void* const* d_in, const int* in_sizes, int n_in,
                              void* d_out, int out_size)
{
    const float* x      = (const float*)d_in[0];
    const float* w_qkv  = (const float*)d_in[1];
    const float* b_qkv  = (const float*)d_in[2];
    const float* w_proj = (const float*)d_in[3];
    const float* b_proj = (const float*)d_in[4];
    float* out = (float*)d_out;

    float* qkv;
    __nv_bfloat16 *xh, *xl, *wqh, *wql, *wph, *wpl, *ah, *al;
    cudaGetSymbolAddress((void**)&qkv, g_qkv);
    cudaGetSymbolAddress((void**)&xh,  g_xh);
    cudaGetSymbolAddress((void**)&xl,  g_xl);
    cudaGetSymbolAddress((void**)&wqh, g_wqh);
    cudaGetSymbolAddress((void**)&wql, g_wql);
    cudaGetSymbolAddress((void**)&wph, g_wph);
    cudaGetSymbolAddress((void**)&wpl, g_wpl);
    cudaGetSymbolAddress((void**)&ah,  g_ah);
    cudaGetSymbolAddress((void**)&al,  g_al);

    static bool attr_set = false;
    if (!attr_set) {
        cudaFuncSetAttribute(gemm_split_mma,
                             cudaFuncAttributeMaxDynamicSharedMemorySize, GEMM_SMEM);
        attr_set = true;
    }

    // 0) precision splits
    split_bf16<<<(NROWS * DM / 4 + 255) / 256, 256>>>((const float4*)x, xh, xl, NROWS * DM / 4);
    split_bf16<<<(QKV_N * DM / 4 + 255) / 256, 256>>>((const float4*)w_qkv, wqh, wql, QKV_N * DM / 4);
    split_bf16<<<(DM * DM / 4 + 255) / 256, 256>>>((const float4*)w_proj, wph, wpl, DM * DM / 4);

    // 1) qkv = x @ w_qkv^T + b_qkv   [4096,1536]  tile 128x64 -> 768 CTAs
    gemm_split_mma<<<dim3(QKV_N / 64, NROWS / 128), 256, GEMM_SMEM>>>(
        QKV_N, DM / 32, xh, xl, wqh, wql, b_qkv, qkv);

    // 2) local windowed attention -> hi/lo bf16 [4096,512]  (2 rows/warp)
    local_attn<<<NROWS / 2 / 8, 256>>>(qkv, ah, al);

    // 3) out = att @ w_proj^T + b_proj   tile 128x64 -> 256 CTAs
    gemm_split_mma<<<dim3(DM / 64, NROWS / 128), 256, GEMM_SMEM>>>(
        DM, DM / 32, ah, al, wph, wpl, b_proj, out);
}

// round 8
// speedup vs baseline: 1.7255x; 1.5481x over previous
#include <cuda_runtime.h>
#include <cuda_fp16.h>
#include <cstdint>

#define T_SEQ   2048
#define BATCH   2
#define DM      512
#define NROWS   (BATCH * T_SEQ)   // 4096
#define QKV_N   (3 * DM)          // 1536
#define WIN     32
#define WW      (2 * WIN - 1)     // 63

// ---------------- scratch (__device__ globals: allocation-free rule) -------
__device__ float g_qkv[NROWS * QKV_N];       // fp32 q|k|v for attention
__device__ __half g_xh[NROWS * DM];          // fp16 x
__device__ __half g_wqh[QKV_N * DM];         // fp16 w_qkv
__device__ __half g_wph[DM * DM];            // fp16 w_proj
__device__ __half g_ah[NROWS * DM];          // fp16 attention output

// ---------------- helpers ---------------------------------------------------
__device__ __forceinline__ uint32_t smem_u32(const void* p) {
    uint32_t a;
    asm("{ .reg .u64 t; cvta.to.shared.u64 t, %1; cvt.u32.u64 %0, t; }"
        : "=r"(a) : "l"(p));
    return a;
}

__device__ __forceinline__ void mma_fp16(float* c, const uint32_t* a, const uint32_t* b) {
    asm volatile(
        "mma.sync.aligned.m16n8k16.row.col.f32.f16.f16.f32 "
        "{%0,%1,%2,%3}, {%4,%5,%6,%7}, {%8,%9}, {%0,%1,%2,%3};"
        : "+f"(c[0]), "+f"(c[1]), "+f"(c[2]), "+f"(c[3])
        : "r"(a[0]), "r"(a[1]), "r"(a[2]), "r"(a[3]), "r"(b[0]), "r"(b[1]));
}

__device__ __forceinline__ void ldm_x4(uint32_t* d, uint32_t addr) {
    asm volatile("ldmatrix.sync.aligned.m8n8.x4.shared.b16 {%0,%1,%2,%3}, [%4];"
                 : "=r"(d[0]), "=r"(d[1]), "=r"(d[2]), "=r"(d[3]) : "r"(addr));
}
__device__ __forceinline__ void ldm_x2(uint32_t* d, uint32_t addr) {
    asm volatile("ldmatrix.sync.aligned.m8n8.x2.shared.b16 {%0,%1}, [%2];"
                 : "=r"(d[0]), "=r"(d[1]) : "r"(addr));
}

// smem geometry: K-chunk 64 fp16 (128B) + 16B pad -> 144B row stride.
// Bank check: stride 36 words; 8-row ldmatrix phase hits banks {0,4,..,28}+c
// -> conflict-free.
#define ROWB    144
#define TILEB_A (128 * ROWB)                 // 18432 B : [128 x 64fp16]
#define TILEB_B (64  * ROWB)                 // 9216  B : [64  x 64fp16]
#define STAGEB  (TILEB_A + TILEB_B)          // 27648 B
#define GEMM_SMEM (2 * STAGEB)               // 55296 B double buffered

// ---------------------------------------------------------------------------
// fp32 -> fp16 convert (vectorized)
// ---------------------------------------------------------------------------
__global__ __launch_bounds__(256) void conv_fp16(
    const float4* __restrict__ src, __half* __restrict__ dst, int n4)
{
    int i = blockIdx.x * blockDim.x + threadIdx.x;
    if (i >= n4) return;
    float4 v = src[i];
    __half2 lo = __floats2half2_rn(v.x, v.y);
    __half2 hi = __floats2half2_rn(v.z, v.w);
    uint2 r;
    r.x = *reinterpret_cast<uint32_t*>(&lo);
    r.y = *reinterpret_cast<uint32_t*>(&hi);
    reinterpret_cast<uint2*>(dst)[i] = r;
}

// ---------------------------------------------------------------------------
// fp16 HMMA GEMM: C[M,Ntot] = A[M,K] @ B[Ntot,K]^T + bias (fp32 accum)
// CTA tile 128x64, 8 warps x (32x32), K-chunk 64, cp.async double buffer.
// ---------------------------------------------------------------------------
__global__ __launch_bounds__(256, 3) void gemm_fp16(
    int Ntot, int kchunks,
    const __half* __restrict__ A, const __half* __restrict__ B,
    const float* __restrict__ bias, float* __restrict__ C)
{
    extern __shared__ __align__(16) char smem[];
    const uint32_t sbase = smem_u32(smem);

    const int tid    = threadIdx.x;
    const int wid    = tid >> 5;
    const int lane   = tid & 31;
    const int l4     = lane >> 2;
    const int lq     = lane & 3;
    const int warp_m = (wid & 3) * 32;
    const int warp_n = (wid >> 2) * 32;
    const int m0     = blockIdx.y * 128;
    const int n0     = blockIdx.x * 64;
    const int K      = kchunks * 64;

    const int g8 = lane >> 3;
    const int r8 = lane & 7;
    const uint32_t a_off = (uint32_t)((warp_m + (g8 & 1) * 8 + r8) * ROWB + (g8 >> 1) * 16);
    const uint32_t b_off = (uint32_t)((warp_n + r8) * ROWB + ((lane >> 3) & 1) * 16);

    // stage loader: A 1024 granules (16B), B 512 granules
    auto issue_stage = [&](int c, int buf) {
#pragma unroll
        for (int j = 0; j < 4; j++) {
            const int idx = tid + 256 * j;           // 0..1023
            const int row = idx >> 3;
            const int c16 = idx & 7;
            const __half* gp = A + (size_t)(m0 + row) * K + c * 64 + c16 * 8;
            const uint32_t sa = sbase + buf * STAGEB + row * ROWB + c16 * 16;
            asm volatile("cp.async.cg.shared.global [%0], [%1], 16;"
                         :: "r"(sa), "l"(gp) : "memory");
        }
#pragma unroll
        for (int j = 0; j < 2; j++) {
            const int idx = tid + 256 * j;           // 0..511
            const int row = idx >> 3;
            const int c16 = idx & 7;
            const __half* gp = B + (size_t)(n0 + row) * K + c * 64 + c16 * 8;
            const uint32_t sa = sbase + buf * STAGEB + TILEB_A + row * ROWB + c16 * 16;
            asm volatile("cp.async.cg.shared.global [%0], [%1], 16;"
                         :: "r"(sa), "l"(gp) : "memory");
        }
        asm volatile("cp.async.commit_group;" ::: "memory");
    };

    float acc[2][4][4];
#pragma unroll
    for (int i = 0; i < 2; i++)
#pragma unroll
        for (int j = 0; j < 4; j++)
#pragma unroll
            for (int r = 0; r < 4; r++) acc[i][j][r] = 0.0f;

    issue_stage(0, 0);
    if (kchunks > 1) issue_stage(1, 1);

    for (int c = 0; c < kchunks; c++) {
        const int buf = c & 1;
        if (c + 1 < kchunks) asm volatile("cp.async.wait_group 1;" ::: "memory");
        else                 asm volatile("cp.async.wait_group 0;" ::: "memory");
        __syncthreads();

        const uint32_t Ab = sbase + buf * STAGEB;
        const uint32_t Bb = Ab + TILEB_A;

#pragma unroll
        for (int kk = 0; kk < 4; kk++) {
            uint32_t a[2][4];
#pragma unroll
            for (int mt = 0; mt < 2; mt++)
                ldm_x4(a[mt], Ab + a_off + mt * 16 * ROWB + kk * 32);
#pragma unroll
            for (int nt = 0; nt < 4; nt++) {
                uint32_t b[2];
                ldm_x2(b, Bb + b_off + nt * 8 * ROWB + kk * 32);
#pragma unroll
                for (int mt = 0; mt < 2; mt++)
                    mma_fp16(acc[mt][nt], a[mt], b);
            }
        }

        __syncthreads();
        if (c + 2 < kchunks) issue_stage(c + 2, buf);
    }

    // ---- epilogue: fp32 + bias ----
#pragma unroll
    for (int nt = 0; nt < 4; nt++) {
        const int col = n0 + warp_n + nt * 8 + 2 * lq;
        const float2 bv = *reinterpret_cast<const float2*>(bias + col);
#pragma unroll
        for (int mt = 0; mt < 2; mt++) {
            const int row = m0 + warp_m + mt * 16 + l4;
            float2 r0, r1;
            r0.x = acc[mt][nt][0] + bv.x;
            r0.y = acc[mt][nt][1] + bv.y;
            r1.x = acc[mt][nt][2] + bv.x;
            r1.y = acc[mt][nt][3] + bv.y;
            *reinterpret_cast<float2*>(C + (size_t)row * Ntot + col) = r0;
            *reinterpret_cast<float2*>(C + (size_t)(row + 8) * Ntot + col) = r1;
        }
    }
}

// ---------------------------------------------------------------------------
// Local windowed attention: 1 warp = 2 rows, float4 loads, fp16 output.
// ---------------------------------------------------------------------------
__global__ __launch_bounds__(256) void local_attn(
    const float* __restrict__ qkv, __half* __restrict__ oh)
{
    const int lane = threadIdx.x & 31;
    const int wg   = (blockIdx.x * blockDim.x + threadIdx.x) >> 5;
    const int m0   = wg * 2;
    const int t0   = m0 & (T_SEQ - 1);

    const float NEG = -1e30f;
    const float inv_scale = 1.0f / 22.62741699796952f;  // 1/sqrt(512)

    float4 q[2][4];
#pragma unroll
    for (int dt = 0; dt < 2; dt++) {
        const float* qp = qkv + (size_t)(m0 + dt) * QKV_N + lane * 4;
#pragma unroll
        for (int g = 0; g < 4; g++)
            q[dt][g] = *reinterpret_cast<const float4*>(qp + 128 * g);
    }

    float s[2][2] = {{NEG, NEG}, {NEG, NEG}};

    for (int d = -(WIN - 1); d <= WIN; d++) {
        const int rt = t0 + d;
        if (rt < 0 || rt >= T_SEQ) continue;
        const float* kp = qkv + (size_t)(m0 + d) * QKV_N + DM + lane * 4;
        float4 kr[4];
#pragma unroll
        for (int g = 0; g < 4; g++)
            kr[g] = *reinterpret_cast<const float4*>(kp + 128 * g);

#pragma unroll
        for (int dt = 0; dt < 2; dt++) {
            const int w = d - dt + (WIN - 1);
            if (w < 0 || w >= WW) continue;
            float dot = 0.0f;
#pragma unroll
            for (int g = 0; g < 4; g++) {
                dot = fmaf(q[dt][g].x, kr[g].x, dot);
                dot = fmaf(q[dt][g].y, kr[g].y, dot);
                dot = fmaf(q[dt][g].z, kr[g].z, dot);
                dot = fmaf(q[dt][g].w, kr[g].w, dot);
            }
#pragma unroll
            for (int o = 16; o > 0; o >>= 1)
                dot += __shfl_xor_sync(0xffffffffu, dot, o);
            if (lane == (w & 31)) s[dt][w >> 5] = dot;
        }
    }

#pragma unroll
    for (int dt = 0; dt < 2; dt++) {
        float s0 = s[dt][0] * inv_scale;
        float s1 = s[dt][1] * inv_scale;
        float mx = fmaxf(s0, s1);
#pragma unroll
        for (int o = 16; o > 0; o >>= 1)
            mx = fmaxf(mx, __shfl_xor_sync(0xffffffffu, mx, o));
        float e0 = __expf(s0 - mx);
        float e1 = __expf(s1 - mx);
        float sum = e0 + e1;
#pragma unroll
        for (int o = 16; o > 0; o >>= 1)
            sum += __shfl_xor_sync(0xffffffffu, sum, o);
        float inv = 1.0f / sum;
        s[dt][0] = e0 * inv;
        s[dt][1] = e1 * inv;
    }

    float4 o[2][4];
#pragma unroll
    for (int dt = 0; dt < 2; dt++)
#pragma unroll
        for (int g = 0; g < 4; g++)
            o[dt][g] = make_float4(0.f, 0.f, 0.f, 0.f);

    for (int d = -(WIN - 1); d <= WIN; d++) {
        const int rt = t0 + d;
        if (rt < 0 || rt >= T_SEQ) continue;
        const float* vp = qkv + (size_t)(m0 + d) * QKV_N + 2 * DM + lane * 4;
        float4 vr[4];
#pragma unroll
        for (int g = 0; g < 4; g++)
            vr[g] = *reinterpret_cast<const float4*>(vp + 128 * g);

#pragma unroll
        for (int dt = 0; dt < 2; dt++) {
            const int w = d - dt + (WIN - 1);
            if (w < 0 || w >= WW) continue;
            const float p = __shfl_sync(0xffffffffu, s[dt][w >> 5], w & 31);
#pragma unroll
            for (int g = 0; g < 4; g++) {
                o[dt][g].x = fmaf(p, vr[g].x, o[dt][g].x);
                o[dt][g].y = fmaf(p, vr[g].y, o[dt][g].y);
                o[dt][g].z = fmaf(p, vr[g].z, o[dt][g].z);
                o[dt][g].w = fmaf(p, vr[g].w, o[dt][g].w);
            }
        }
    }

    // write fp16 output
#pragma unroll
    for (int dt = 0; dt < 2; dt++) {
        const size_t base = (size_t)(m0 + dt) * DM + lane * 4;
#pragma unroll
        for (int g = 0; g < 4; g++) {
            __half2 lo = __floats2half2_rn(o[dt][g].x, o[dt][g].y);
            __half2 hi = __floats2half2_rn(o[dt][g].z, o[dt][g].w);
            uint2 r;
            r.x = *reinterpret_cast<uint32_t*>(&lo);
            r.y = *reinterpret_cast<uint32_t*>(&hi);
            *reinterpret_cast<uint2*>(oh + base + 128 * g) = r;
        }
    }
}

// ---------------------------------------------------------------------------
extern "C" void kernel_launch(void* const* d_in, const int* in_sizes, int n_in,
                              void* d_out, int out_size)
{
    const float* x      = (const float*)d_in[0];
    const float* w_qkv  = (const float*)d_in[1];
    const float* b_qkv  = (const float*)d_in[2];
    const float* w_proj = (const float*)d_in[3];
    const float* b_proj = (const float*)d_in[4];
    float* out = (float*)d_out;

    float* qkv;
    __half *xh, *wqh, *wph, *ah;
    cudaGetSymbolAddress((void**)&qkv, g_qkv);
    cudaGetSymbolAddress((void**)&xh,  g_xh);
    cudaGetSymbolAddress((void**)&wqh, g_wqh);
    cudaGetSymbolAddress((void**)&wph, g_wph);
    cudaGetSymbolAddress((void**)&ah,  g_ah);

    static bool attr_set = false;
    if (!attr_set) {
        cudaFuncSetAttribute(gemm_fp16,
                             cudaFuncAttributeMaxDynamicSharedMemorySize, GEMM_SMEM);
        attr_set = true;
    }

    // 0) fp16 converts
    conv_fp16<<<(NROWS * DM / 4 + 255) / 256, 256>>>((const float4*)x, xh, NROWS * DM / 4);
    conv_fp16<<<(QKV_N * DM / 4 + 255) / 256, 256>>>((const float4*)w_qkv, wqh, QKV_N * DM / 4);
    conv_fp16<<<(DM * DM / 4 + 255) / 256, 256>>>((const float4*)w_proj, wph, DM * DM / 4);

    // 1) qkv = x @ w_qkv^T + b_qkv   [4096,1536]
    gemm_fp16<<<dim3(QKV_N / 64, NROWS / 128), 256, GEMM_SMEM>>>(
        QKV_N, DM / 64, xh, wqh, b_qkv, qkv);

    // 2) local windowed attention -> fp16 [4096,512]
    local_attn<<<NROWS / 2 / 8, 256>>>(qkv, ah);

    // 3) out = att @ w_proj^T + b_proj
    gemm_fp16<<<dim3(DM / 64, NROWS / 128), 256, GEMM_SMEM>>>(
        DM, DM / 64, ah, wph, b_proj, out);
}